// round 5
// baseline (speedup 1.0000x reference)
#include <cuda_runtime.h>
#include <math.h>

#define D_MODEL   3072
#define NUM_E     8
#define N_TOKENS  16384
#define TPW       4                       // tokens per warp-quad
#define WARPS_PB  16
#define THREADS   (WARPS_PB * 32)         // 512
#define CHUNK_D   128                     // floats of D per stage
#define NCHUNK    (D_MODEL / CHUNK_D)     // 24
#define NSTAGE    4                       // per-warp ring slots
#define GRID      148
#define NWARPS_G  (GRID * WARPS_PB)       // 2368
#define NQUADS    (N_TOKENS / TPW)        // 4096
#define ROW_V     (D_MODEL / 4)
#define STAGE_BYTES (TPW * CHUNK_D * 4)   // 2048 B per stage
#define RING_FLOATS_PER_WARP (NSTAGE * TPW * CHUNK_D)   // 2048 floats = 8 KB
// smem: [mbar: 16*4*8B =512] [W: 96 KB] [rings: 128 KB]  => 229,888 B
#define SMEM_MBAR_BYTES 512
#define SMEM_BYTES (SMEM_MBAR_BYTES + (NUM_E * D_MODEL + WARPS_PB * RING_FLOATS_PER_WARP) * 4)

typedef unsigned long long u64;

__device__ __forceinline__ u64 ffma2(u64 a, u64 b, u64 c) {
    u64 d;
    asm("fma.rn.f32x2 %0, %1, %2, %3;" : "=l"(d) : "l"(a), "l"(b), "l"(c));
    return d;
}
__device__ __forceinline__ float unpack_sum(u64 v) {
    return __uint_as_float((unsigned)(v & 0xFFFFFFFFull)) +
           __uint_as_float((unsigned)(v >> 32));
}

__global__ void __launch_bounds__(THREADS, 1)
gating_kernel(const float* __restrict__ x,
              const float* __restrict__ W,
              const float* __restrict__ b,
              float* __restrict__ out,
              int idx_off)
{
    extern __shared__ float smem[];
    // layout: mbarriers | W | rings
    u64*   mbar = reinterpret_cast<u64*>(smem);                  // [16][4]
    float* sW   = smem + SMEM_MBAR_BYTES / 4;                    // [8][3072]
    float* sX   = sW + NUM_E * D_MODEL;                          // rings

    const int warp = threadIdx.x >> 5;
    const int lane = threadIdx.x & 31;
    const int bid  = blockIdx.x;

    // Cooperative load of W into shared memory.
    {
        const float4* Wv = reinterpret_cast<const float4*>(W);
        float4* sWv4 = reinterpret_cast<float4*>(sW);
        #pragma unroll 4
        for (int i = threadIdx.x; i < NUM_E * D_MODEL / 4; i += THREADS)
            sWv4[i] = Wv[i];
    }

    // Per-warp mbarrier init (warp-private ring; only warp-level sync needed).
    const unsigned mbar_s =
        (unsigned)__cvta_generic_to_shared(&mbar[warp * NSTAGE]);
    if (lane == 0) {
        #pragma unroll
        for (int s = 0; s < NSTAGE; ++s)
            asm volatile("mbarrier.init.shared.b64 [%0], 1;"
                         :: "r"(mbar_s + s * 8) : "memory");
        asm volatile("fence.proxy.async.shared::cta;" ::: "memory");
    }
    __syncwarp();
    __syncthreads();   // W visible to all warps

    float* ring = sX + warp * RING_FLOATS_PER_WARP;
    const unsigned ring_s = (unsigned)__cvta_generic_to_shared(ring);
    const ulonglong2* __restrict__ ringv =
        reinterpret_cast<const ulonglong2*>(ring);
    const ulonglong2* __restrict__ sWv =
        reinterpret_cast<const ulonglong2*>(sW);

    // Balanced persistent distribution: quads round-robin CTA-first.
    const int q0 = bid + GRID * warp;                 // < 2368
    const int nq = (q0 + NWARPS_G < NQUADS) ? 2 : 1;
    const int T  = nq * NCHUNK;

    // stage t -> quad j = t/24, chunk c = t%24, slot t%4
    #define ISSUE_STAGE(t_)                                                    \
        do {                                                                   \
            if (lane == 0) {                                                   \
                int _t = (t_);                                                 \
                int _j = _t / NCHUNK;                                          \
                int _c = _t - _j * NCHUNK;                                     \
                const float* _src = x + (size_t)(q0 + _j * NWARPS_G)           \
                                        * (TPW * D_MODEL) + _c * CHUNK_D;      \
                unsigned _mb  = mbar_s + (_t % NSTAGE) * 8;                    \
                unsigned _dst = ring_s + (_t % NSTAGE) * STAGE_BYTES;          \
                asm volatile(                                                  \
                    "mbarrier.arrive.expect_tx.shared.b64 _, [%0], %1;"        \
                    :: "r"(_mb), "r"(STAGE_BYTES) : "memory");                 \
                _Pragma("unroll")                                              \
                for (int _tt = 0; _tt < TPW; ++_tt)                            \
                    asm volatile(                                              \
                        "cp.async.bulk.shared::cta.global"                     \
                        ".mbarrier::complete_tx::bytes [%0], [%1], %2, [%3];"  \
                        :: "r"(_dst + _tt * (CHUNK_D * 4)),                    \
                           "l"(_src + (size_t)_tt * D_MODEL),                  \
                           "r"(CHUNK_D * 4), "r"(_mb) : "memory");             \
            }                                                                  \
        } while (0)

    u64 acc[TPW][NUM_E];
    #pragma unroll
    for (int t = 0; t < TPW; ++t)
        #pragma unroll
        for (int e = 0; e < NUM_E; ++e)
            acc[t][e] = 0ull;

    // Prologue: 2 stages in flight.
    ISSUE_STAGE(0);
    ISSUE_STAGE(1);

    for (int t = 0; t < T; ++t) {
        const int slot  = t % NSTAGE;
        const unsigned phase = (unsigned)((t / NSTAGE) & 1);

        // Wait for stage t data (acquire).
        {
            const unsigned mb = mbar_s + slot * 8;
            unsigned done;
            asm volatile(
                "{\n\t.reg .pred p;\n\t"
                "mbarrier.try_wait.parity.acquire.cta.shared::cta.b64 p, [%1], %2;\n\t"
                "selp.b32 %0, 1, 0, p;\n\t}"
                : "=r"(done) : "r"(mb), "r"(phase) : "memory");
            while (!done) {
                asm volatile(
                    "{\n\t.reg .pred p;\n\t"
                    "mbarrier.try_wait.parity.acquire.cta.shared::cta.b64 p, [%1], %2, 0x989680;\n\t"
                    "selp.b32 %0, 1, 0, p;\n\t}"
                    : "=r"(done) : "r"(mb), "r"(phase) : "memory");
            }
        }

        // Refill: slot (t+2)%4 was fully consumed at iteration t-2.
        if (t + 2 < T) ISSUE_STAGE(t + 2);

        const int j = t / NCHUNK;
        const int c = t - j * NCHUNK;

        const ulonglong2* xs = ringv + slot * (TPW * CHUNK_D / 4);
        ulonglong2 xv[TPW];
        #pragma unroll
        for (int tt = 0; tt < TPW; ++tt)
            xv[tt] = xs[tt * (CHUNK_D / 4) + lane];

        #pragma unroll
        for (int e = 0; e < NUM_E; ++e) {
            const ulonglong2 wv = sWv[e * ROW_V + c * (CHUNK_D / 4) + lane];
            #pragma unroll
            for (int tt = 0; tt < TPW; ++tt) {
                acc[tt][e] = ffma2(xv[tt].x, wv.x, acc[tt][e]);
                acc[tt][e] = ffma2(xv[tt].y, wv.y, acc[tt][e]);
            }
        }

        if (c == NCHUNK - 1) {
            // ---- epilogue for quad q0 + j*NWARPS_G ----
            const int tok0 = (q0 + j * NWARPS_G) * TPW;

            float red[TPW][NUM_E];
            #pragma unroll
            for (int tt = 0; tt < TPW; ++tt)
                #pragma unroll
                for (int e = 0; e < NUM_E; ++e) {
                    red[tt][e] = unpack_sum(acc[tt][e]);
                    acc[tt][e] = 0ull;
                }

            #pragma unroll
            for (int off = 16; off > 0; off >>= 1)
                #pragma unroll
                for (int tt = 0; tt < TPW; ++tt)
                    #pragma unroll
                    for (int e = 0; e < NUM_E; ++e)
                        red[tt][e] += __shfl_xor_sync(0xFFFFFFFFu, red[tt][e], off);

            if (lane < TPW) {
                const int tok = tok0 + lane;

                float logit[NUM_E];
                #pragma unroll
                for (int e = 0; e < NUM_E; ++e)
                    logit[e] = red[lane][e] + __ldg(&b[e]);

                float m = logit[0];
                #pragma unroll
                for (int e = 1; e < NUM_E; ++e) m = fmaxf(m, logit[e]);

                float ex[NUM_E], Z = 0.0f;
                #pragma unroll
                for (int e = 0; e < NUM_E; ++e) { ex[e] = __expf(logit[e] - m); Z += ex[e]; }
                const float invZ = 1.0f / Z;

                float sc[NUM_E];
                #pragma unroll
                for (int e = 0; e < NUM_E; ++e) sc[e] = ex[e] * invZ;

                int i1 = 0;
                #pragma unroll
                for (int e = 1; e < NUM_E; ++e) if (sc[e] > sc[i1]) i1 = e;
                int i2 = (i1 == 0) ? 1 : 0;
                #pragma unroll
                for (int e = 0; e < NUM_E; ++e)
                    if (e != i1 && sc[e] > sc[i2]) i2 = e;

                const float v1 = sc[i1];
                const float v2 = sc[i2];
                const float e2 = __expf(v2 - v1);
                const float r1 = 1.0f / (1.0f + e2);
                const float r2 = 1.0f - r1;

                out[(size_t)tok * 2 + 0] = r1;
                out[(size_t)tok * 2 + 1] = r2;
                out[(size_t)idx_off + (size_t)tok * 2 + 0] = (float)i1;
                out[(size_t)idx_off + (size_t)tok * 2 + 1] = (float)i2;
            }
        }
    }
    #undef ISSUE_STAGE
}

extern "C" void kernel_launch(void* const* d_in, const int* in_sizes, int n_in,
                              void* d_out, int out_size)
{
    const float* x = (const float*)d_in[0];
    const float* W = (const float*)d_in[1];
    const float* b = (const float*)d_in[2];
    float* out = (float*)d_out;

    const int idx_off = out_size / 2;

    cudaFuncSetAttribute(gating_kernel,
                         cudaFuncAttributeMaxDynamicSharedMemorySize,
                         (int)SMEM_BYTES);

    gating_kernel<<<GRID, THREADS, SMEM_BYTES>>>(x, W, b, out, idx_off);
}

// round 6
// speedup vs baseline: 1.0391x; 1.0391x over previous
#include <cuda_runtime.h>
#include <math.h>

#define D_MODEL   3072
#define NUM_E     8
#define N_TOKENS  16384
#define TPW       4                       // tokens per warp-quad
#define WARPS_PB  16
#define THREADS   (WARPS_PB * 32)         // 512
#define CHUNK_D   128                     // floats of D per pipeline stage
#define NCHUNK    (D_MODEL / CHUNK_D)     // 24
#define NSTAGE    4                       // per-warp ring depth
#define GRID      128                     // 2048 warps -> exactly 2 quads each
#define NWARPS_G  (GRID * WARPS_PB)       // 2048
#define NQUADS    (N_TOKENS / TPW)        // 4096
#define NQ        (NQUADS / NWARPS_G)     // 2 quads per warp, uniform
#define T_STAGES  (NQ * NCHUNK)           // 48
#define ROW_V     (D_MODEL / 4)
#define RING_FLOATS_PER_WARP (NSTAGE * TPW * CHUNK_D)    // 2048 floats = 8 KB
#define SMEM_BYTES ((NUM_E * D_MODEL + WARPS_PB * RING_FLOATS_PER_WARP) * 4)  // 224 KB

typedef unsigned long long u64;

__device__ __forceinline__ u64 ffma2(u64 a, u64 b, u64 c) {
    u64 d;
    asm("fma.rn.f32x2 %0, %1, %2, %3;" : "=l"(d) : "l"(a), "l"(b), "l"(c));
    return d;
}
__device__ __forceinline__ float unpack_sum(u64 v) {
    return __uint_as_float((unsigned)(v & 0xFFFFFFFFull)) +
           __uint_as_float((unsigned)(v >> 32));
}

__global__ void __launch_bounds__(THREADS, 1)
gating_kernel(const float* __restrict__ x,
              const float* __restrict__ W,
              const float* __restrict__ b,
              float* __restrict__ out,
              int idx_off)
{
    extern __shared__ float smem[];
    float* sW = smem;                                   // [8][3072]
    float* sX = smem + NUM_E * D_MODEL;                 // per-warp rings

    {
        const float4* Wv = reinterpret_cast<const float4*>(W);
        float4* sWv4 = reinterpret_cast<float4*>(sW);
        #pragma unroll 4
        for (int i = threadIdx.x; i < NUM_E * D_MODEL / 4; i += THREADS)
            sWv4[i] = Wv[i];
    }
    __syncthreads();

    const int warp = threadIdx.x >> 5;
    const int lane = threadIdx.x & 31;
    const int bid  = blockIdx.x;

    float* ring = sX + warp * RING_FLOATS_PER_WARP;
    const unsigned ring_s =
        (unsigned)__cvta_generic_to_shared(ring) + lane * 16;
    const ulonglong2* __restrict__ ringv =
        reinterpret_cast<const ulonglong2*>(ring);
    const ulonglong2* __restrict__ sWv =
        reinterpret_cast<const ulonglong2*>(sW);

    // Uniform schedule: quads q0 and q0 + 2048, 48 stages for every warp.
    const int q0 = bid + GRID * warp;     // < 2048

    // stage t -> quad j = t/24, chunk c = t%24, ring slot t%4
    #define ISSUE_STAGE(t_)                                                   \
        do {                                                                  \
            int _t = (t_);                                                    \
            int _j = _t / NCHUNK;                                             \
            int _c = _t - _j * NCHUNK;                                        \
            const float* _src = x + (size_t)(q0 + _j * NWARPS_G)              \
                                    * (TPW * D_MODEL)                         \
                                  + _c * CHUNK_D + lane * 4;                  \
            unsigned _dst = ring_s + (_t % NSTAGE) * (TPW * CHUNK_D * 4);     \
            _Pragma("unroll")                                                 \
            for (int _tt = 0; _tt < TPW; ++_tt)                               \
                asm volatile("cp.async.cg.shared.global [%0], [%1], 16;"      \
                             :: "r"(_dst + _tt * (CHUNK_D * 4)),              \
                                "l"(_src + (size_t)_tt * D_MODEL));           \
        } while (0)

    u64 acc[TPW][NUM_E];
    #pragma unroll
    for (int t = 0; t < TPW; ++t)
        #pragma unroll
        for (int e = 0; e < NUM_E; ++e)
            acc[t][e] = 0ull;

    // Prologue: 3 stages in flight.
    ISSUE_STAGE(0);
    asm volatile("cp.async.commit_group;" ::: "memory");
    ISSUE_STAGE(1);
    asm volatile("cp.async.commit_group;" ::: "memory");
    ISSUE_STAGE(2);
    asm volatile("cp.async.commit_group;" ::: "memory");

    for (int t = 0; t < T_STAGES; ++t) {
        // stage t complete (<=2 younger groups still pending)
        asm volatile("cp.async.wait_group 2;" ::: "memory");

        // Refill slot (t+3)%4: consumed at iteration t-1; safe.
        if (t + 3 < T_STAGES) ISSUE_STAGE(t + 3);
        asm volatile("cp.async.commit_group;" ::: "memory");

        const int j = t / NCHUNK;
        const int c = t - j * NCHUNK;
        const int slot = t % NSTAGE;

        const ulonglong2* xs = ringv + slot * (TPW * CHUNK_D / 4);
        ulonglong2 xv[TPW];
        #pragma unroll
        for (int tt = 0; tt < TPW; ++tt)
            xv[tt] = xs[tt * (CHUNK_D / 4) + lane];

        #pragma unroll
        for (int e = 0; e < NUM_E; ++e) {
            const ulonglong2 wv = sWv[e * ROW_V + c * (CHUNK_D / 4) + lane];
            #pragma unroll
            for (int tt = 0; tt < TPW; ++tt) {
                acc[tt][e] = ffma2(xv[tt].x, wv.x, acc[tt][e]);
                acc[tt][e] = ffma2(xv[tt].y, wv.y, acc[tt][e]);
            }
        }

        if (c == NCHUNK - 1) {
            // ---- epilogue for quad q = q0 + j*NWARPS_G ----
            const int tok0 = (q0 + j * NWARPS_G) * TPW;

            float red[TPW][NUM_E];
            #pragma unroll
            for (int tt = 0; tt < TPW; ++tt)
                #pragma unroll
                for (int e = 0; e < NUM_E; ++e) {
                    red[tt][e] = unpack_sum(acc[tt][e]);
                    acc[tt][e] = 0ull;
                }

            #pragma unroll
            for (int off = 16; off > 0; off >>= 1)
                #pragma unroll
                for (int tt = 0; tt < TPW; ++tt)
                    #pragma unroll
                    for (int e = 0; e < NUM_E; ++e)
                        red[tt][e] += __shfl_xor_sync(0xFFFFFFFFu, red[tt][e], off);

            if (lane < TPW) {
                const int tok = tok0 + lane;

                float logit[NUM_E];
                #pragma unroll
                for (int e = 0; e < NUM_E; ++e)
                    logit[e] = red[lane][e] + __ldg(&b[e]);

                float m = logit[0];
                #pragma unroll
                for (int e = 1; e < NUM_E; ++e) m = fmaxf(m, logit[e]);

                float ex[NUM_E], Z = 0.0f;
                #pragma unroll
                for (int e = 0; e < NUM_E; ++e) { ex[e] = __expf(logit[e] - m); Z += ex[e]; }
                const float invZ = 1.0f / Z;

                float sc[NUM_E];
                #pragma unroll
                for (int e = 0; e < NUM_E; ++e) sc[e] = ex[e] * invZ;

                int i1 = 0;
                #pragma unroll
                for (int e = 1; e < NUM_E; ++e) if (sc[e] > sc[i1]) i1 = e;
                int i2 = (i1 == 0) ? 1 : 0;
                #pragma unroll
                for (int e = 0; e < NUM_E; ++e)
                    if (e != i1 && sc[e] > sc[i2]) i2 = e;

                const float v1 = sc[i1];
                const float v2 = sc[i2];
                const float e2 = __expf(v2 - v1);
                const float r1 = 1.0f / (1.0f + e2);
                const float r2 = 1.0f - r1;

                out[(size_t)tok * 2 + 0] = r1;
                out[(size_t)tok * 2 + 1] = r2;
                out[(size_t)idx_off + (size_t)tok * 2 + 0] = (float)i1;
                out[(size_t)idx_off + (size_t)tok * 2 + 1] = (float)i2;
            }
        }
    }
    #undef ISSUE_STAGE
}

extern "C" void kernel_launch(void* const* d_in, const int* in_sizes, int n_in,
                              void* d_out, int out_size)
{
    const float* x = (const float*)d_in[0];
    const float* W = (const float*)d_in[1];
    const float* b = (const float*)d_in[2];
    float* out = (float*)d_out;

    const int idx_off = out_size / 2;

    cudaFuncSetAttribute(gating_kernel,
                         cudaFuncAttributeMaxDynamicSharedMemorySize,
                         (int)SMEM_BYTES);

    gating_kernel<<<GRID, THREADS, SMEM_BYTES>>>(x, W, b, out, idx_off);
}